// round 6
// baseline (speedup 1.0000x reference)
#include <cuda_runtime.h>
#include <cuda_fp16.h>
#include <cstdint>

// Problem constants
#define BB 4
#define SS 2048
#define DD 1024
#define MM (BB * SS)   // 8192

#define NEG_INF (__int_as_float(0xff800000))

// GEMM tiling (R4 config): CTA 256x128, 8 warps of 64x64, BK=32, 4-stage cp.async
#define CTA_M 256
#define CTA_N 128
#define BK 32
#define TPB 256
#define NSTAGE 4
#define A_BYTES (CTA_M * 64)          // 256 rows x 64B (32 fp16)
#define B_BYTES (CTA_N * 64)          // 128 rows x 64B
#define STAGE_BYTES (A_BYTES + B_BYTES)   // 24576
#define SMEM_DYN (NSTAGE * STAGE_BYTES + 1024)   // 99328 (>= 67.6KB transpose stage)

// -------- device scratch (allocation-free rule: __device__ globals) --------
__device__ __half g_xh [(size_t)MM * DD];
__device__ __half g_Wth[(size_t)3 * DD * DD];     // [z][n][k] = W[z][k][n]
__device__ __half g_Qh [(size_t)MM * DD];
__device__ __half g_Kh [(size_t)MM * DD];
__device__ __half g_Vth[(size_t)BB * DD * SS];    // [b][d][s] (written by qkv z==2)
__device__ float  g_P  [(size_t)BB * SS * SS];    // fp32 scores
__device__ __half g_Ph [(size_t)BB * SS * SS];    // fp16 probabilities (zero-init tail)

__device__ __forceinline__ uint32_t smem_u32(const void* p) {
    uint32_t a;
    asm("{ .reg .u64 t; cvta.to.shared.u64 t, %1; cvt.u32.u64 %0, t; }" : "=r"(a) : "l"(p));
    return a;
}
#define SWZ64(x) ((x) ^ (((x) >> 3) & 0x30u))

// ---------------------------------------------------------------------------
// fp16 tensor-core mainloop (identical to Round-4). CTA computes 256x128.
// A row-major [256][lda] fp16; B row-major [128][ldb] fp16 (rows = N dim).
// acc[i][j][4]: warp 64x64 = 4 m16 x 8 n8 tiles.
// ---------------------------------------------------------------------------
__device__ __forceinline__ void gemm_f16(
    const __half* __restrict__ A, const __half* __restrict__ B,
    int lda, int ldb, int kTotal, float acc[4][8][4])
{
    extern __shared__ char smem_raw[];
    const uint32_t base = (smem_u32(smem_raw) + 1023) & ~1023u;
    const int tid = threadIdx.x, L = tid & 31, wid = tid >> 5;
    const int wm = (wid & 3) * 64, wn = (wid >> 2) * 64;

    uint32_t offA[4][2], offB[4][2];
    {
        const int ra = wm + (L & 15);
        const int ca = (L >> 4);
        #pragma unroll
        for (int i = 0; i < 4; ++i)
            #pragma unroll
            for (int h = 0; h < 2; ++h) {
                uint32_t o = (uint32_t)(ra + i * 16) * 64u + (uint32_t)(h * 2 + ca) * 16u;
                offA[i][h] = SWZ64(o);
            }
        const int rb = wn + ((L >> 4) & 1) * 8 + (L & 7);
        const int cb = (L >> 3) & 1;
        #pragma unroll
        for (int jj = 0; jj < 4; ++jj)
            #pragma unroll
            for (int h = 0; h < 2; ++h) {
                uint32_t o = (uint32_t)(rb + jj * 16) * 64u + (uint32_t)(h * 2 + cb) * 16u;
                offB[jj][h] = (uint32_t)A_BYTES + SWZ64(o);
            }
    }

    const int nslab = kTotal / BK;

    auto issue = [&](int s) {
        const uint32_t sb = base + (uint32_t)(s & (NSTAGE - 1)) * STAGE_BYTES;
        const int k0 = s * BK;
        #pragma unroll
        for (int i = 0; i < 4; ++i) {
            const int g = i * 256 + tid;
            const int row = g >> 2, ch = g & 3;
            const uint32_t dst = sb + SWZ64((uint32_t)row * 64u + (uint32_t)ch * 16u);
            const __half* src = A + (size_t)row * lda + k0 + ch * 8;
            asm volatile("cp.async.cg.shared.global [%0], [%1], 16;" :: "r"(dst), "l"(src));
        }
        #pragma unroll
        for (int i = 0; i < 2; ++i) {
            const int g = i * 256 + tid;
            const int row = g >> 2, ch = g & 3;
            const uint32_t dst = sb + (uint32_t)A_BYTES
                               + SWZ64((uint32_t)row * 64u + (uint32_t)ch * 16u);
            const __half* src = B + (size_t)row * ldb + k0 + ch * 8;
            asm volatile("cp.async.cg.shared.global [%0], [%1], 16;" :: "r"(dst), "l"(src));
        }
        asm volatile("cp.async.commit_group;" ::: "memory");
    };

    issue(0); issue(1); issue(2);

    for (int t = 0; t < nslab; ++t) {
        asm volatile("cp.async.wait_group 2;" ::: "memory");
        __syncthreads();
        if (t + 3 < nslab) issue(t + 3);
        else asm volatile("cp.async.commit_group;" ::: "memory");

        const uint32_t sb = base + (uint32_t)(t & (NSTAGE - 1)) * STAGE_BYTES;
        #pragma unroll
        for (int h = 0; h < 2; ++h) {
            uint32_t a[4][4], b[4][4];
            #pragma unroll
            for (int i = 0; i < 4; ++i)
                asm volatile("ldmatrix.sync.aligned.m8n8.x4.shared.b16 {%0,%1,%2,%3}, [%4];"
                    : "=r"(a[i][0]), "=r"(a[i][1]), "=r"(a[i][2]), "=r"(a[i][3])
                    : "r"(sb + offA[i][h]));
            #pragma unroll
            for (int jj = 0; jj < 4; ++jj)
                asm volatile("ldmatrix.sync.aligned.m8n8.x4.shared.b16 {%0,%1,%2,%3}, [%4];"
                    : "=r"(b[jj][0]), "=r"(b[jj][1]), "=r"(b[jj][2]), "=r"(b[jj][3])
                    : "r"(sb + offB[jj][h]));
            #pragma unroll
            for (int i = 0; i < 4; ++i)
                #pragma unroll
                for (int j = 0; j < 8; ++j) {
                    asm volatile(
                        "mma.sync.aligned.m16n8k16.row.col.f32.f16.f16.f32 "
                        "{%0,%1,%2,%3},{%4,%5,%6,%7},{%8,%9},{%0,%1,%2,%3};"
                        : "+f"(acc[i][j][0]), "+f"(acc[i][j][1]),
                          "+f"(acc[i][j][2]), "+f"(acc[i][j][3])
                        : "r"(a[i][0]), "r"(a[i][1]), "r"(a[i][2]), "r"(a[i][3]),
                          "r"(b[j >> 1][(j & 1) * 2]), "r"(b[j >> 1][(j & 1) * 2 + 1]));
                }
        }
    }
    asm volatile("cp.async.wait_group 0;" ::: "memory");
}

// ============================ GEMM kernels ============================

// QKV: C[m][n] = sum_k xh[m][k] * Wth[z][n][k].  grid (D/128, M/256, 3)
// z==0 -> Qh, z==1 -> Kh (row-major); z==2 -> Vth (transposed via smem stage).
__global__ __launch_bounds__(TPB, 2) void qkv_f16()
{
    const int m0 = blockIdx.y * CTA_M, n0 = blockIdx.x * CTA_N;
    const int z = blockIdx.z;
    const __half* Bp = g_Wth + (size_t)z * DD * DD + (size_t)n0 * DD;

    float acc[4][8][4] = {};
    gemm_f16(g_xh + (size_t)m0 * DD, Bp, DD, DD, DD, acc);

    const int tid = threadIdx.x, L = tid & 31, wid = tid >> 5;
    const int wm = (wid & 3) * 64, wn = (wid >> 2) * 64;

    if (z < 2) {
        __half* C = (z == 0) ? g_Qh : g_Kh;
        #pragma unroll
        for (int i = 0; i < 4; ++i) {
            const int row = m0 + wm + i * 16 + (L >> 2);
            #pragma unroll
            for (int j = 0; j < 8; ++j) {
                const int col = n0 + wn + j * 8 + (L & 3) * 2;
                *(__half2*)&C[(size_t)row * DD + col]       = __floats2half2_rn(acc[i][j][0], acc[i][j][1]);
                *(__half2*)&C[(size_t)(row + 8) * DD + col] = __floats2half2_rn(acc[i][j][2], acc[i][j][3]);
            }
        }
    } else {
        // transpose-in-smem epilogue: st[d (128)][s (256, pad to 264)]
        extern __shared__ char smem_raw[];
        __half* st = (__half*)smem_raw;
        __syncthreads();   // mainloop smem no longer needed by any warp
        #pragma unroll
        for (int i = 0; i < 4; ++i) {
            const int rs = wm + i * 16 + (L >> 2);
            #pragma unroll
            for (int j = 0; j < 8; ++j) {
                const int cd = wn + j * 8 + (L & 3) * 2;
                st[cd * 264 + rs]           = __float2half(acc[i][j][0]);
                st[(cd + 1) * 264 + rs]     = __float2half(acc[i][j][1]);
                st[cd * 264 + rs + 8]       = __float2half(acc[i][j][2]);
                st[(cd + 1) * 264 + rs + 8] = __float2half(acc[i][j][3]);
            }
        }
        __syncthreads();
        const int b = m0 >> 11;          // 2048 rows per batch
        const int s0 = m0 & 2047;
        #pragma unroll
        for (int it = 0; it < 16; ++it) {
            const int d = it * 8 + (tid >> 5);
            const int s = (tid & 31) * 8;
            const uint4 v = *(const uint4*)&st[d * 264 + s];
            *(uint4*)&g_Vth[((size_t)b * DD + n0 + d) * SS + s0 + s] = v;
        }
    }
}

// scores: P[q][k] = mask(Q·K^T / 32).  grid (S/128 kblk, S/256 qblk, B)
__global__ __launch_bounds__(TPB, 2) void scores_f16()
{
    const int qblk = blockIdx.y, kblk = blockIdx.x, b = blockIdx.z;
    if (kblk * CTA_N >= (qblk + 1) * CTA_M) return;
    const int q0 = qblk * CTA_M, k0 = kblk * CTA_N;

    float acc[4][8][4] = {};
    gemm_f16(g_Qh + ((size_t)b * SS + q0) * DD,
             g_Kh + ((size_t)b * SS + k0) * DD, DD, DD, DD, acc);

    const int L = threadIdx.x & 31, wid = threadIdx.x >> 5;
    const int wm = (wid & 3) * 64, wn = (wid >> 2) * 64;
    float* P = g_P + (size_t)b * SS * SS;
    #pragma unroll
    for (int i = 0; i < 4; ++i) {
        #pragma unroll
        for (int j = 0; j < 8; ++j) {
            const int col = k0 + wn + j * 8 + (L & 3) * 2;
            #pragma unroll
            for (int h = 0; h < 2; ++h) {
                const int row = q0 + wm + i * 16 + (L >> 2) + h * 8;
                float v0 = acc[i][j][2 * h + 0] * 0.03125f;
                float v1 = acc[i][j][2 * h + 1] * 0.03125f;
                if (col > row)     v0 = NEG_INF;
                if (col + 1 > row) v1 = NEG_INF;
                *(float2*)&P[(size_t)row * SS + col] = make_float2(v0, v1);
            }
        }
    }
}

// PV: O[q][n] = sum_k Ph[q][k] * Vth[n][k].  grid (D/128, S/256, B)
__global__ __launch_bounds__(TPB, 2) void pv_f16(float* __restrict__ out)
{
    const int b = blockIdx.z;
    const int q0 = blockIdx.y * CTA_M, n0 = blockIdx.x * CTA_N;
    const int kTotal = (blockIdx.y + 1) * CTA_M;

    float acc[4][8][4] = {};
    gemm_f16(g_Ph + ((size_t)b * SS + q0) * SS,
             g_Vth + ((size_t)b * DD + n0) * SS, SS, SS, kTotal, acc);

    const int L = threadIdx.x & 31, wid = threadIdx.x >> 5;
    const int wm = (wid & 3) * 64, wn = (wid >> 2) * 64;
    float* C = out + (size_t)b * SS * DD;
    #pragma unroll
    for (int i = 0; i < 4; ++i) {
        const int row = q0 + wm + i * 16 + (L >> 2);
        #pragma unroll
        for (int j = 0; j < 8; ++j) {
            const int col = n0 + wn + j * 8 + (L & 3) * 2;
            *(float2*)&C[(size_t)row * DD + col]       = make_float2(acc[i][j][0], acc[i][j][1]);
            *(float2*)&C[(size_t)(row + 8) * DD + col] = make_float2(acc[i][j][2], acc[i][j][3]);
        }
    }
}

// ============================ aux kernels ============================

__global__ void cvt_x_kernel(const float* __restrict__ x)
{
    const size_t i = ((size_t)blockIdx.x * blockDim.x + threadIdx.x) * 4;
    const float4 v = *(const float4*)(x + i);
    *(__half2*)(g_xh + i)     = __floats2half2_rn(v.x, v.y);
    *(__half2*)(g_xh + i + 2) = __floats2half2_rn(v.z, v.w);
}

__global__ void transW_kernel(const float* __restrict__ Wq,
                              const float* __restrict__ Wk,
                              const float* __restrict__ Wv)
{
    __shared__ float tile[32][33];
    const float* W = (blockIdx.z == 0) ? Wq : (blockIdx.z == 1) ? Wk : Wv;
    __half* Wt = g_Wth + (size_t)blockIdx.z * DD * DD;
    const int x0 = blockIdx.x * 32, y0 = blockIdx.y * 32;
    for (int i = threadIdx.y; i < 32; i += 8)
        tile[i][threadIdx.x] = W[(size_t)(y0 + i) * DD + x0 + threadIdx.x];
    __syncthreads();
    for (int i = threadIdx.y; i < 32; i += 8)
        Wt[(size_t)(x0 + i) * DD + y0 + threadIdx.x] = __float2half(tile[threadIdx.x][i]);
}

// row softmax g_P (fp32) -> g_Ph (fp16); valid region [0, Lp), Lp 128-aligned.
// Ph beyond Lp is never written: __device__ globals are zero-initialized and
// those columns are exactly the masked ones, so PV reads true zeros there.
__global__ __launch_bounds__(256) void softmax_kernel()
{
    const int q = blockIdx.x, b = blockIdx.y;
    const float* row = g_P + ((size_t)b * SS + q) * SS;
    __half* orow = g_Ph + ((size_t)b * SS + q) * SS;
    const int Lp = ((q >> 7) + 1) << 7;
    const int tid = threadIdx.x, L = tid & 31, wid = tid >> 5;

    float vals[8];
    float m = NEG_INF;
    #pragma unroll
    for (int i = 0; i < 8; ++i) {
        const int idx = tid + i * 256;
        vals[i] = (idx < Lp) ? row[idx] : NEG_INF;
        m = fmaxf(m, vals[i]);
    }
    #pragma unroll
    for (int off = 16; off > 0; off >>= 1)
        m = fmaxf(m, __shfl_xor_sync(0xFFFFFFFFu, m, off));
    __shared__ float sm[8], ssum[8];
    if (L == 0) sm[wid] = m;
    __syncthreads();
    m = sm[0];
    #pragma unroll
    for (int w = 1; w < 8; ++w) m = fmaxf(m, sm[w]);

    float sum = 0.f;
    #pragma unroll
    for (int i = 0; i < 8; ++i) {
        const float t = vals[i] - m;
        vals[i] = (t < -80.f) ? 0.f : __expf(t);
        sum += vals[i];
    }
    #pragma unroll
    for (int off = 16; off > 0; off >>= 1)
        sum += __shfl_xor_sync(0xFFFFFFFFu, sum, off);
    if (L == 0) ssum[wid] = sum;
    __syncthreads();
    float tot = ssum[0];
    #pragma unroll
    for (int w = 1; w < 8; ++w) tot += ssum[w];
    const float inv = 1.f / tot;

    #pragma unroll
    for (int i = 0; i < 8; ++i) {
        const int idx = tid + i * 256;
        if (idx < Lp) orow[idx] = __float2half(vals[i] * inv);
    }
}

// ---------------------------------------------------------------------------
extern "C" void kernel_launch(void* const* d_in, const int* in_sizes, int n_in,
                              void* d_out, int out_size)
{
    const float* x  = (const float*)d_in[0];
    const float* Wq = (const float*)d_in[1];
    const float* Wk = (const float*)d_in[2];
    const float* Wv = (const float*)d_in[3];
    float* out = (float*)d_out;
    (void)in_sizes; (void)n_in; (void)out_size;

    cudaFuncSetAttribute(qkv_f16,    cudaFuncAttributeMaxDynamicSharedMemorySize, SMEM_DYN);
    cudaFuncSetAttribute(scores_f16, cudaFuncAttributeMaxDynamicSharedMemorySize, SMEM_DYN);
    cudaFuncSetAttribute(pv_f16,     cudaFuncAttributeMaxDynamicSharedMemorySize, SMEM_DYN);

    cvt_x_kernel<<<(int)(((size_t)MM * DD / 4) / 256), 256>>>(x);
    transW_kernel<<<dim3(32, 32, 3), dim3(32, 8)>>>(Wq, Wk, Wv);
    qkv_f16<<<dim3(DD / CTA_N, MM / CTA_M, 3), TPB, SMEM_DYN>>>();
    scores_f16<<<dim3(SS / CTA_N, SS / CTA_M, BB), TPB, SMEM_DYN>>>();
    softmax_kernel<<<dim3(SS, BB), 256>>>();
    pv_f16<<<dim3(DD / CTA_N, SS / CTA_M, BB), TPB, SMEM_DYN>>>(out);
}

// round 7
// speedup vs baseline: 1.8831x; 1.8831x over previous
#include <cuda_runtime.h>
#include <cuda_fp16.h>
#include <cstdint>

// Problem constants
#define BB 4
#define SS 2048
#define DD 1024
#define MM (BB * SS)   // 8192

#define NEG_INF (__int_as_float(0xff800000))

// GEMM tiling (R4 config): CTA 256x128, 8 warps of 64x64, BK=32, 4-stage cp.async
#define CTA_M 256
#define CTA_N 128
#define BK 32
#define TPB 256
#define NSTAGE 4
#define A_BYTES (CTA_M * 64)          // 256 rows x 64B (32 fp16)
#define B_BYTES (CTA_N * 64)          // 128 rows x 64B
#define STAGE_BYTES (A_BYTES + B_BYTES)   // 24576
#define SMEM_DYN (NSTAGE * STAGE_BYTES + 1024)   // 99328 (>= 67.6KB transpose stage)

// -------- device scratch (allocation-free rule: __device__ globals) --------
__device__ __half g_xh [(size_t)MM * DD];
__device__ __half g_Wth[(size_t)3 * DD * DD];     // [z][n][k] = W[z][k][n]
__device__ __half g_Qh [(size_t)MM * DD];
__device__ __half g_Kh [(size_t)MM * DD];
__device__ __half g_Vth[(size_t)BB * DD * SS];    // [b][d][s] (written by qkv z==2)
__device__ float  g_P  [(size_t)BB * SS * SS];    // fp32 scores
__device__ __half g_Ph [(size_t)BB * SS * SS];    // fp16 probabilities (zero-init tail)

__device__ __forceinline__ uint32_t smem_u32(const void* p) {
    uint32_t a;
    asm("{ .reg .u64 t; cvta.to.shared.u64 t, %1; cvt.u32.u64 %0, t; }" : "=r"(a) : "l"(p));
    return a;
}
#define SWZ64(x) ((x) ^ (((x) >> 3) & 0x30u))

// ---------------------------------------------------------------------------
// fp16 tensor-core mainloop (R4-identical). CTA computes 256x128.
// A row-major [256][lda] fp16; B row-major [128][ldb] fp16 (rows = N dim).
// acc[i][j][4]: warp 64x64 = 4 m16 x 8 n8 tiles.
// ---------------------------------------------------------------------------
__device__ __forceinline__ void gemm_f16(
    const __half* __restrict__ A, const __half* __restrict__ B,
    int lda, int ldb, int kTotal, float acc[4][8][4])
{
    extern __shared__ char smem_raw[];
    const uint32_t base = (smem_u32(smem_raw) + 1023) & ~1023u;
    const int tid = threadIdx.x, L = tid & 31, wid = tid >> 5;
    const int wm = (wid & 3) * 64, wn = (wid >> 2) * 64;

    uint32_t offA[4][2], offB[4][2];
    {
        const int ra = wm + (L & 15);
        const int ca = (L >> 4);
        #pragma unroll
        for (int i = 0; i < 4; ++i)
            #pragma unroll
            for (int h = 0; h < 2; ++h) {
                uint32_t o = (uint32_t)(ra + i * 16) * 64u + (uint32_t)(h * 2 + ca) * 16u;
                offA[i][h] = SWZ64(o);
            }
        const int rb = wn + ((L >> 4) & 1) * 8 + (L & 7);
        const int cb = (L >> 3) & 1;
        #pragma unroll
        for (int jj = 0; jj < 4; ++jj)
            #pragma unroll
            for (int h = 0; h < 2; ++h) {
                uint32_t o = (uint32_t)(rb + jj * 16) * 64u + (uint32_t)(h * 2 + cb) * 16u;
                offB[jj][h] = (uint32_t)A_BYTES + SWZ64(o);
            }
    }

    const int nslab = kTotal / BK;

    auto issue = [&](int s) {
        const uint32_t sb = base + (uint32_t)(s & (NSTAGE - 1)) * STAGE_BYTES;
        const int k0 = s * BK;
        #pragma unroll
        for (int i = 0; i < 4; ++i) {
            const int g = i * 256 + tid;
            const int row = g >> 2, ch = g & 3;
            const uint32_t dst = sb + SWZ64((uint32_t)row * 64u + (uint32_t)ch * 16u);
            const __half* src = A + (size_t)row * lda + k0 + ch * 8;
            asm volatile("cp.async.cg.shared.global [%0], [%1], 16;" :: "r"(dst), "l"(src));
        }
        #pragma unroll
        for (int i = 0; i < 2; ++i) {
            const int g = i * 256 + tid;
            const int row = g >> 2, ch = g & 3;
            const uint32_t dst = sb + (uint32_t)A_BYTES
                               + SWZ64((uint32_t)row * 64u + (uint32_t)ch * 16u);
            const __half* src = B + (size_t)row * ldb + k0 + ch * 8;
            asm volatile("cp.async.cg.shared.global [%0], [%1], 16;" :: "r"(dst), "l"(src));
        }
        asm volatile("cp.async.commit_group;" ::: "memory");
    };

    issue(0); issue(1); issue(2);

    for (int t = 0; t < nslab; ++t) {
        asm volatile("cp.async.wait_group 2;" ::: "memory");
        __syncthreads();
        if (t + 3 < nslab) issue(t + 3);
        else asm volatile("cp.async.commit_group;" ::: "memory");

        const uint32_t sb = base + (uint32_t)(t & (NSTAGE - 1)) * STAGE_BYTES;
        #pragma unroll
        for (int h = 0; h < 2; ++h) {
            uint32_t a[4][4], b[4][4];
            #pragma unroll
            for (int i = 0; i < 4; ++i)
                asm volatile("ldmatrix.sync.aligned.m8n8.x4.shared.b16 {%0,%1,%2,%3}, [%4];"
                    : "=r"(a[i][0]), "=r"(a[i][1]), "=r"(a[i][2]), "=r"(a[i][3])
                    : "r"(sb + offA[i][h]));
            #pragma unroll
            for (int jj = 0; jj < 4; ++jj)
                asm volatile("ldmatrix.sync.aligned.m8n8.x4.shared.b16 {%0,%1,%2,%3}, [%4];"
                    : "=r"(b[jj][0]), "=r"(b[jj][1]), "=r"(b[jj][2]), "=r"(b[jj][3])
                    : "r"(sb + offB[jj][h]));
            #pragma unroll
            for (int i = 0; i < 4; ++i)
                #pragma unroll
                for (int j = 0; j < 8; ++j) {
                    asm volatile(
                        "mma.sync.aligned.m16n8k16.row.col.f32.f16.f16.f32 "
                        "{%0,%1,%2,%3},{%4,%5,%6,%7},{%8,%9},{%0,%1,%2,%3};"
                        : "+f"(acc[i][j][0]), "+f"(acc[i][j][1]),
                          "+f"(acc[i][j][2]), "+f"(acc[i][j][3])
                        : "r"(a[i][0]), "r"(a[i][1]), "r"(a[i][2]), "r"(a[i][3]),
                          "r"(b[j >> 1][(j & 1) * 2]), "r"(b[j >> 1][(j & 1) * 2 + 1]));
                }
        }
    }
    asm volatile("cp.async.wait_group 0;" ::: "memory");
}

// ============================ GEMM kernels ============================

// QKV: C[m][n] = sum_k xh[m][k] * Wth[z][n][k].  grid (D/128, M/256, 3)
// z==0 -> Qh, z==1 -> Kh (row-major); z==2 -> Vth (transposed via smem stage).
__global__ __launch_bounds__(TPB) void qkv_f16()
{
    const int m0 = blockIdx.y * CTA_M, n0 = blockIdx.x * CTA_N;
    const int z = blockIdx.z;
    const __half* Bp = g_Wth + (size_t)z * DD * DD + (size_t)n0 * DD;

    float acc[4][8][4] = {};
    gemm_f16(g_xh + (size_t)m0 * DD, Bp, DD, DD, DD, acc);

    const int tid = threadIdx.x, L = tid & 31, wid = tid >> 5;
    const int wm = (wid & 3) * 64, wn = (wid >> 2) * 64;

    if (z < 2) {
        __half* C = (z == 0) ? g_Qh : g_Kh;
        #pragma unroll
        for (int i = 0; i < 4; ++i) {
            const int row = m0 + wm + i * 16 + (L >> 2);
            #pragma unroll
            for (int j = 0; j < 8; ++j) {
                const int col = n0 + wn + j * 8 + (L & 3) * 2;
                *(__half2*)&C[(size_t)row * DD + col]       = __floats2half2_rn(acc[i][j][0], acc[i][j][1]);
                *(__half2*)&C[(size_t)(row + 8) * DD + col] = __floats2half2_rn(acc[i][j][2], acc[i][j][3]);
            }
        }
    } else {
        // transpose-in-smem epilogue: st[d (128)][s (256, pad to 264)]
        extern __shared__ char smem_raw[];
        __half* st = (__half*)smem_raw;
        __syncthreads();   // mainloop smem no longer needed by any warp
        #pragma unroll
        for (int i = 0; i < 4; ++i) {
            const int rs = wm + i * 16 + (L >> 2);
            #pragma unroll
            for (int j = 0; j < 8; ++j) {
                const int cd = wn + j * 8 + (L & 3) * 2;
                st[cd * 264 + rs]           = __float2half(acc[i][j][0]);
                st[(cd + 1) * 264 + rs]     = __float2half(acc[i][j][1]);
                st[cd * 264 + rs + 8]       = __float2half(acc[i][j][2]);
                st[(cd + 1) * 264 + rs + 8] = __float2half(acc[i][j][3]);
            }
        }
        __syncthreads();
        const int b = m0 >> 11;          // 2048 rows per batch
        const int s0 = m0 & 2047;
        #pragma unroll
        for (int it = 0; it < 16; ++it) {
            const int d = it * 8 + (tid >> 5);
            const int s = (tid & 31) * 8;
            const uint4 v = *(const uint4*)&st[d * 264 + s];
            *(uint4*)&g_Vth[((size_t)b * DD + n0 + d) * SS + s0 + s] = v;
        }
    }
}

// scores: P[q][k] = mask(Q·K^T / 32).  grid (S/128 kblk, S/256 qblk, B)
__global__ __launch_bounds__(TPB) void scores_f16()
{
    const int qblk = blockIdx.y, kblk = blockIdx.x, b = blockIdx.z;
    if (kblk * CTA_N >= (qblk + 1) * CTA_M) return;
    const int q0 = qblk * CTA_M, k0 = kblk * CTA_N;

    float acc[4][8][4] = {};
    gemm_f16(g_Qh + ((size_t)b * SS + q0) * DD,
             g_Kh + ((size_t)b * SS + k0) * DD, DD, DD, DD, acc);

    const int L = threadIdx.x & 31, wid = threadIdx.x >> 5;
    const int wm = (wid & 3) * 64, wn = (wid >> 2) * 64;
    float* P = g_P + (size_t)b * SS * SS;
    #pragma unroll
    for (int i = 0; i < 4; ++i) {
        #pragma unroll
        for (int j = 0; j < 8; ++j) {
            const int col = k0 + wn + j * 8 + (L & 3) * 2;
            #pragma unroll
            for (int h = 0; h < 2; ++h) {
                const int row = q0 + wm + i * 16 + (L >> 2) + h * 8;
                float v0 = acc[i][j][2 * h + 0] * 0.03125f;
                float v1 = acc[i][j][2 * h + 1] * 0.03125f;
                if (col > row)     v0 = NEG_INF;
                if (col + 1 > row) v1 = NEG_INF;
                *(float2*)&P[(size_t)row * SS + col] = make_float2(v0, v1);
            }
        }
    }
}

// PV: O[q][n] = sum_k Ph[q][k] * Vth[n][k].  grid (D/128, S/256, B)
__global__ __launch_bounds__(TPB) void pv_f16(float* __restrict__ out)
{
    const int b = blockIdx.z;
    const int q0 = blockIdx.y * CTA_M, n0 = blockIdx.x * CTA_N;
    const int kTotal = (blockIdx.y + 1) * CTA_M;

    float acc[4][8][4] = {};
    gemm_f16(g_Ph + ((size_t)b * SS + q0) * SS,
             g_Vth + ((size_t)b * DD + n0) * SS, SS, SS, kTotal, acc);

    const int L = threadIdx.x & 31, wid = threadIdx.x >> 5;
    const int wm = (wid & 3) * 64, wn = (wid >> 2) * 64;
    float* C = out + (size_t)b * SS * DD;
    #pragma unroll
    for (int i = 0; i < 4; ++i) {
        const int row = q0 + wm + i * 16 + (L >> 2);
        #pragma unroll
        for (int j = 0; j < 8; ++j) {
            const int col = n0 + wn + j * 8 + (L & 3) * 2;
            *(float2*)&C[(size_t)row * DD + col]       = make_float2(acc[i][j][0], acc[i][j][1]);
            *(float2*)&C[(size_t)(row + 8) * DD + col] = make_float2(acc[i][j][2], acc[i][j][3]);
        }
    }
}

// ============================ aux kernels ============================

__global__ void cvt_x_kernel(const float* __restrict__ x)
{
    const size_t i = ((size_t)blockIdx.x * blockDim.x + threadIdx.x) * 4;
    const float4 v = *(const float4*)(x + i);
    *(__half2*)(g_xh + i)     = __floats2half2_rn(v.x, v.y);
    *(__half2*)(g_xh + i + 2) = __floats2half2_rn(v.z, v.w);
}

__global__ void transW_kernel(const float* __restrict__ Wq,
                              const float* __restrict__ Wk,
                              const float* __restrict__ Wv)
{
    __shared__ float tile[32][33];
    const float* W = (blockIdx.z == 0) ? Wq : (blockIdx.z == 1) ? Wk : Wv;
    __half* Wt = g_Wth + (size_t)blockIdx.z * DD * DD;
    const int x0 = blockIdx.x * 32, y0 = blockIdx.y * 32;
    for (int i = threadIdx.y; i < 32; i += 8)
        tile[i][threadIdx.x] = W[(size_t)(y0 + i) * DD + x0 + threadIdx.x];
    __syncthreads();
    for (int i = threadIdx.y; i < 32; i += 8)
        Wt[(size_t)(x0 + i) * DD + y0 + threadIdx.x] = __float2half(tile[threadIdx.x][i]);
}

// row softmax g_P (fp32) -> g_Ph (fp16); valid region [0, Lp), Lp 128-aligned.
// Ph beyond Lp is never written: __device__ globals are zero-initialized and
// those columns are exactly the masked ones, so PV reads true zeros there.
__global__ __launch_bounds__(256) void softmax_kernel()
{
    const int q = blockIdx.x, b = blockIdx.y;
    const float* row = g_P + ((size_t)b * SS + q) * SS;
    __half* orow = g_Ph + ((size_t)b * SS + q) * SS;
    const int Lp = ((q >> 7) + 1) << 7;
    const int tid = threadIdx.x, L = tid & 31, wid = tid >> 5;

    float vals[8];
    float m = NEG_INF;
    #pragma unroll
    for (int i = 0; i < 8; ++i) {
        const int idx = tid + i * 256;
        vals[i] = (idx < Lp) ? row[idx] : NEG_INF;
        m = fmaxf(m, vals[i]);
    }
    #pragma unroll
    for (int off = 16; off > 0; off >>= 1)
        m = fmaxf(m, __shfl_xor_sync(0xFFFFFFFFu, m, off));
    __shared__ float sm[8], ssum[8];
    if (L == 0) sm[wid] = m;
    __syncthreads();
    m = sm[0];
    #pragma unroll
    for (int w = 1; w < 8; ++w) m = fmaxf(m, sm[w]);

    float sum = 0.f;
    #pragma unroll
    for (int i = 0; i < 8; ++i) {
        const float t = vals[i] - m;
        vals[i] = (t < -80.f) ? 0.f : __expf(t);
        sum += vals[i];
    }
    #pragma unroll
    for (int off = 16; off > 0; off >>= 1)
        sum += __shfl_xor_sync(0xFFFFFFFFu, sum, off);
    if (L == 0) ssum[wid] = sum;
    __syncthreads();
    float tot = ssum[0];
    #pragma unroll
    for (int w = 1; w < 8; ++w) tot += ssum[w];
    const float inv = 1.f / tot;

    #pragma unroll
    for (int i = 0; i < 8; ++i) {
        const int idx = tid + i * 256;
        if (idx < Lp) orow[idx] = __float2half(vals[i] * inv);
    }
}

// ---------------------------------------------------------------------------
extern "C" void kernel_launch(void* const* d_in, const int* in_sizes, int n_in,
                              void* d_out, int out_size)
{
    const float* x  = (const float*)d_in[0];
    const float* Wq = (const float*)d_in[1];
    const float* Wk = (const float*)d_in[2];
    const float* Wv = (const float*)d_in[3];
    float* out = (float*)d_out;
    (void)in_sizes; (void)n_in; (void)out_size;

    cudaFuncSetAttribute(qkv_f16,    cudaFuncAttributeMaxDynamicSharedMemorySize, SMEM_DYN);
    cudaFuncSetAttribute(scores_f16, cudaFuncAttributeMaxDynamicSharedMemorySize, SMEM_DYN);
    cudaFuncSetAttribute(pv_f16,     cudaFuncAttributeMaxDynamicSharedMemorySize, SMEM_DYN);

    cvt_x_kernel<<<(int)(((size_t)MM * DD / 4) / 256), 256>>>(x);
    transW_kernel<<<dim3(32, 32, 3), dim3(32, 8)>>>(Wq, Wk, Wv);
    qkv_f16<<<dim3(DD / CTA_N, MM / CTA_M, 3), TPB, SMEM_DYN>>>();
    scores_f16<<<dim3(SS / CTA_N, SS / CTA_M, BB), TPB, SMEM_DYN>>>();
    softmax_kernel<<<dim3(SS, BB), 256>>>();
    pv_f16<<<dim3(DD / CTA_N, SS / CTA_M, BB), TPB, SMEM_DYN>>>(out);
}

// round 8
// speedup vs baseline: 2.6516x; 1.4081x over previous
#include <cuda_runtime.h>
#include <cuda_fp16.h>
#include <cstdint>

// Problem constants
#define BB 4
#define SS 2048
#define DD 1024
#define MM (BB * SS)   // 8192

#define NEG_INF (__int_as_float(0xff800000))

// GEMM tiling: CTA 128x128, 4 warps (128 thr) of 64x64, BK=32, 4-stage cp.async
#define CTA_M 128
#define CTA_N 128
#define BK 32
#define TPB 128
#define NSTAGE 4
#define A_BYTES (CTA_M * 64)          // 128 rows x 64B (32 fp16)
#define B_BYTES (CTA_N * 64)          // 128 rows x 64B
#define STAGE_BYTES (A_BYTES + B_BYTES)   // 16384
#define SMEM_DYN (NSTAGE * STAGE_BYTES + 1024)   // 66560 (>= 34.8KB transpose stage)

// -------- device scratch (allocation-free rule: __device__ globals) --------
__device__ __half g_xh [(size_t)MM * DD];
__device__ __half g_Wth[(size_t)3 * DD * DD];     // [z][n][k] = W[z][k][n]
__device__ __half g_Qh [(size_t)MM * DD];
__device__ __half g_Kh [(size_t)MM * DD];
__device__ __half g_Vth[(size_t)BB * DD * SS];    // [b][d][s] (written by qkv z==2)
__device__ float  g_P  [(size_t)BB * SS * SS];    // fp32 scores
__device__ __half g_Ph [(size_t)BB * SS * SS];    // fp16 probabilities (zero-init tail)

__device__ __forceinline__ uint32_t smem_u32(const void* p) {
    uint32_t a;
    asm("{ .reg .u64 t; cvta.to.shared.u64 t, %1; cvt.u32.u64 %0, t; }" : "=r"(a) : "l"(p));
    return a;
}
#define SWZ64(x) ((x) ^ (((x) >> 3) & 0x30u))

// ---------------------------------------------------------------------------
// fp16 tensor-core mainloop. CTA computes 128x128, 4 warps in 2x2 (64x64 each).
// A row-major [128][lda] fp16; B row-major [128][ldb] fp16 (rows = N dim).
// acc[i][j][4]: 4 m16 x 8 n8 tiles per warp.
// ---------------------------------------------------------------------------
__device__ __forceinline__ void gemm_f16(
    const __half* __restrict__ A, const __half* __restrict__ B,
    int lda, int ldb, int kTotal, float acc[4][8][4])
{
    extern __shared__ char smem_raw[];
    const uint32_t base = (smem_u32(smem_raw) + 1023) & ~1023u;
    const int tid = threadIdx.x, L = tid & 31, wid = tid >> 5;
    const int wm = (wid & 1) * 64, wn = (wid >> 1) * 64;

    uint32_t offA[4][2], offB[4][2];
    {
        const int ra = wm + (L & 15);
        const int ca = (L >> 4);
        #pragma unroll
        for (int i = 0; i < 4; ++i)
            #pragma unroll
            for (int h = 0; h < 2; ++h) {
                uint32_t o = (uint32_t)(ra + i * 16) * 64u + (uint32_t)(h * 2 + ca) * 16u;
                offA[i][h] = SWZ64(o);
            }
        const int rb = wn + ((L >> 4) & 1) * 8 + (L & 7);
        const int cb = (L >> 3) & 1;
        #pragma unroll
        for (int jj = 0; jj < 4; ++jj)
            #pragma unroll
            for (int h = 0; h < 2; ++h) {
                uint32_t o = (uint32_t)(rb + jj * 16) * 64u + (uint32_t)(h * 2 + cb) * 16u;
                offB[jj][h] = (uint32_t)A_BYTES + SWZ64(o);
            }
    }

    const int nslab = kTotal / BK;

    auto issue = [&](int s) {
        const uint32_t sb = base + (uint32_t)(s & (NSTAGE - 1)) * STAGE_BYTES;
        const int k0 = s * BK;
        #pragma unroll
        for (int i = 0; i < 4; ++i) {               // A: 512 16B chunks
            const int g = i * TPB + tid;
            const int row = g >> 2, ch = g & 3;
            const uint32_t dst = sb + SWZ64((uint32_t)row * 64u + (uint32_t)ch * 16u);
            const __half* src = A + (size_t)row * lda + k0 + ch * 8;
            asm volatile("cp.async.cg.shared.global [%0], [%1], 16;" :: "r"(dst), "l"(src));
        }
        #pragma unroll
        for (int i = 0; i < 4; ++i) {               // B: 512 16B chunks
            const int g = i * TPB + tid;
            const int row = g >> 2, ch = g & 3;
            const uint32_t dst = sb + (uint32_t)A_BYTES
                               + SWZ64((uint32_t)row * 64u + (uint32_t)ch * 16u);
            const __half* src = B + (size_t)row * ldb + k0 + ch * 8;
            asm volatile("cp.async.cg.shared.global [%0], [%1], 16;" :: "r"(dst), "l"(src));
        }
        asm volatile("cp.async.commit_group;" ::: "memory");
    };

    issue(0); issue(1); issue(2);

    for (int t = 0; t < nslab; ++t) {
        asm volatile("cp.async.wait_group 2;" ::: "memory");
        __syncthreads();
        if (t + 3 < nslab) issue(t + 3);
        else asm volatile("cp.async.commit_group;" ::: "memory");

        const uint32_t sb = base + (uint32_t)(t & (NSTAGE - 1)) * STAGE_BYTES;
        #pragma unroll
        for (int h = 0; h < 2; ++h) {
            uint32_t a[4][4], b[4][4];
            #pragma unroll
            for (int i = 0; i < 4; ++i)
                asm volatile("ldmatrix.sync.aligned.m8n8.x4.shared.b16 {%0,%1,%2,%3}, [%4];"
                    : "=r"(a[i][0]), "=r"(a[i][1]), "=r"(a[i][2]), "=r"(a[i][3])
                    : "r"(sb + offA[i][h]));
            #pragma unroll
            for (int jj = 0; jj < 4; ++jj)
                asm volatile("ldmatrix.sync.aligned.m8n8.x4.shared.b16 {%0,%1,%2,%3}, [%4];"
                    : "=r"(b[jj][0]), "=r"(b[jj][1]), "=r"(b[jj][2]), "=r"(b[jj][3])
                    : "r"(sb + offB[jj][h]));
            #pragma unroll
            for (int i = 0; i < 4; ++i)
                #pragma unroll
                for (int j = 0; j < 8; ++j) {
                    asm volatile(
                        "mma.sync.aligned.m16n8k16.row.col.f32.f16.f16.f32 "
                        "{%0,%1,%2,%3},{%4,%5,%6,%7},{%8,%9},{%0,%1,%2,%3};"
                        : "+f"(acc[i][j][0]), "+f"(acc[i][j][1]),
                          "+f"(acc[i][j][2]), "+f"(acc[i][j][3])
                        : "r"(a[i][0]), "r"(a[i][1]), "r"(a[i][2]), "r"(a[i][3]),
                          "r"(b[j >> 1][(j & 1) * 2]), "r"(b[j >> 1][(j & 1) * 2 + 1]));
                }
        }
    }
    asm volatile("cp.async.wait_group 0;" ::: "memory");
}

// ============================ GEMM kernels ============================

// QKV: C[m][n] = sum_k xh[m][k] * Wth[z][n][k].  grid (D/128, M/128, 3)
// z==0 -> Qh, z==1 -> Kh (row-major); z==2 -> Vth (transposed via smem stage).
__global__ __launch_bounds__(TPB) void qkv_f16()
{
    const int m0 = blockIdx.y * CTA_M, n0 = blockIdx.x * CTA_N;
    const int z = blockIdx.z;
    const __half* Bp = g_Wth + (size_t)z * DD * DD + (size_t)n0 * DD;

    float acc[4][8][4] = {};
    gemm_f16(g_xh + (size_t)m0 * DD, Bp, DD, DD, DD, acc);

    const int tid = threadIdx.x, L = tid & 31, wid = tid >> 5;
    const int wm = (wid & 1) * 64, wn = (wid >> 1) * 64;

    if (z < 2) {
        __half* C = (z == 0) ? g_Qh : g_Kh;
        #pragma unroll
        for (int i = 0; i < 4; ++i) {
            const int row = m0 + wm + i * 16 + (L >> 2);
            #pragma unroll
            for (int j = 0; j < 8; ++j) {
                const int col = n0 + wn + j * 8 + (L & 3) * 2;
                *(__half2*)&C[(size_t)row * DD + col]       = __floats2half2_rn(acc[i][j][0], acc[i][j][1]);
                *(__half2*)&C[(size_t)(row + 8) * DD + col] = __floats2half2_rn(acc[i][j][2], acc[i][j][3]);
            }
        }
    } else {
        // transpose-in-smem epilogue: st[d (128)][s (128, pad to 136)]
        extern __shared__ char smem_raw[];
        __half* st = (__half*)smem_raw;
        __syncthreads();   // mainloop smem dead
        #pragma unroll
        for (int i = 0; i < 4; ++i) {
            const int rs = wm + i * 16 + (L >> 2);
            #pragma unroll
            for (int j = 0; j < 8; ++j) {
                const int cd = wn + j * 8 + (L & 3) * 2;
                st[cd * 136 + rs]           = __float2half(acc[i][j][0]);
                st[(cd + 1) * 136 + rs]     = __float2half(acc[i][j][1]);
                st[cd * 136 + rs + 8]       = __float2half(acc[i][j][2]);
                st[(cd + 1) * 136 + rs + 8] = __float2half(acc[i][j][3]);
            }
        }
        __syncthreads();
        const int b = m0 >> 11;          // 2048 rows per batch
        const int s0 = m0 & 2047;
        #pragma unroll
        for (int it = 0; it < 16; ++it) {
            const int lin = it * TPB + tid;          // 2048 16B chunks
            const int d = lin >> 4, c = lin & 15;
            const uint4 v = *(const uint4*)&st[d * 136 + c * 8];
            *(uint4*)&g_Vth[((size_t)b * DD + n0 + d) * SS + s0 + c * 8] = v;
        }
    }
}

// scores: P[q][k] = mask(Q·K^T / 32).  grid (S/128 kblk, S/128 qblk, B)
__global__ __launch_bounds__(TPB) void scores_f16()
{
    const int qblk = blockIdx.y, kblk = blockIdx.x, b = blockIdx.z;
    if (kblk > qblk) return;
    const int q0 = qblk * CTA_M, k0 = kblk * CTA_N;

    float acc[4][8][4] = {};
    gemm_f16(g_Qh + ((size_t)b * SS + q0) * DD,
             g_Kh + ((size_t)b * SS + k0) * DD, DD, DD, DD, acc);

    const int L = threadIdx.x & 31, wid = threadIdx.x >> 5;
    const int wm = (wid & 1) * 64, wn = (wid >> 1) * 64;
    float* P = g_P + (size_t)b * SS * SS;
    #pragma unroll
    for (int i = 0; i < 4; ++i) {
        #pragma unroll
        for (int j = 0; j < 8; ++j) {
            const int col = k0 + wn + j * 8 + (L & 3) * 2;
            #pragma unroll
            for (int h = 0; h < 2; ++h) {
                const int row = q0 + wm + i * 16 + (L >> 2) + h * 8;
                float v0 = acc[i][j][2 * h + 0] * 0.03125f;
                float v1 = acc[i][j][2 * h + 1] * 0.03125f;
                if (col > row)     v0 = NEG_INF;
                if (col + 1 > row) v1 = NEG_INF;
                *(float2*)&P[(size_t)row * SS + col] = make_float2(v0, v1);
            }
        }
    }
}

// PV: O[q][n] = sum_k Ph[q][k] * Vth[n][k].  grid (D/128, S/128, B)
__global__ __launch_bounds__(TPB) void pv_f16(float* __restrict__ out)
{
    const int b = blockIdx.z;
    const int q0 = blockIdx.y * CTA_M, n0 = blockIdx.x * CTA_N;
    const int kTotal = (blockIdx.y + 1) * CTA_M;

    float acc[4][8][4] = {};
    gemm_f16(g_Ph + ((size_t)b * SS + q0) * SS,
             g_Vth + ((size_t)b * DD + n0) * SS, SS, SS, kTotal, acc);

    const int L = threadIdx.x & 31, wid = threadIdx.x >> 5;
    const int wm = (wid & 1) * 64, wn = (wid >> 1) * 64;
    float* C = out + (size_t)b * SS * DD;
    #pragma unroll
    for (int i = 0; i < 4; ++i) {
        const int row = q0 + wm + i * 16 + (L >> 2);
        #pragma unroll
        for (int j = 0; j < 8; ++j) {
            const int col = n0 + wn + j * 8 + (L & 3) * 2;
            *(float2*)&C[(size_t)row * DD + col]       = make_float2(acc[i][j][0], acc[i][j][1]);
            *(float2*)&C[(size_t)(row + 8) * DD + col] = make_float2(acc[i][j][2], acc[i][j][3]);
        }
    }
}

// ============================ aux kernels ============================

__global__ void cvt_x_kernel(const float* __restrict__ x)
{
    const size_t i = ((size_t)blockIdx.x * blockDim.x + threadIdx.x) * 4;
    const float4 v = *(const float4*)(x + i);
    *(__half2*)(g_xh + i)     = __floats2half2_rn(v.x, v.y);
    *(__half2*)(g_xh + i + 2) = __floats2half2_rn(v.z, v.w);
}

__global__ void transW_kernel(const float* __restrict__ Wq,
                              const float* __restrict__ Wk,
                              const float* __restrict__ Wv)
{
    __shared__ float tile[32][33];
    const float* W = (blockIdx.z == 0) ? Wq : (blockIdx.z == 1) ? Wk : Wv;
    __half* Wt = g_Wth + (size_t)blockIdx.z * DD * DD;
    const int x0 = blockIdx.x * 32, y0 = blockIdx.y * 32;
    for (int i = threadIdx.y; i < 32; i += 8)
        tile[i][threadIdx.x] = W[(size_t)(y0 + i) * DD + x0 + threadIdx.x];
    __syncthreads();
    for (int i = threadIdx.y; i < 32; i += 8)
        Wt[(size_t)(x0 + i) * DD + y0 + threadIdx.x] = __float2half(tile[threadIdx.x][i]);
}

// row softmax g_P (fp32) -> g_Ph (fp16); valid region [0, Lp), Lp 128-aligned.
// Ph beyond Lp is never written: __device__ globals are zero-initialized and
// those columns are exactly the masked ones, so PV reads true zeros there.
__global__ __launch_bounds__(256) void softmax_kernel()
{
    const int q = blockIdx.x, b = blockIdx.y;
    const float* row = g_P + ((size_t)b * SS + q) * SS;
    __half* orow = g_Ph + ((size_t)b * SS + q) * SS;
    const int Lp = ((q >> 7) + 1) << 7;
    const int tid = threadIdx.x, L = tid & 31, wid = tid >> 5;

    float vals[8];
    float m = NEG_INF;
    #pragma unroll
    for (int i = 0; i < 8; ++i) {
        const int idx = tid + i * 256;
        vals[i] = (idx < Lp) ? row[idx] : NEG_INF;
        m = fmaxf(m, vals[i]);
    }
    #pragma unroll
    for (int off = 16; off > 0; off >>= 1)
        m = fmaxf(m, __shfl_xor_sync(0xFFFFFFFFu, m, off));
    __shared__ float sm[8], ssum[8];
    if (L == 0) sm[wid] = m;
    __syncthreads();
    m = sm[0];
    #pragma unroll
    for (int w = 1; w < 8; ++w) m = fmaxf(m, sm[w]);

    float sum = 0.f;
    #pragma unroll
    for (int i = 0; i < 8; ++i) {
        const float t = vals[i] - m;
        vals[i] = (t < -80.f) ? 0.f : __expf(t);
        sum += vals[i];
    }
    #pragma unroll
    for (int off = 16; off > 0; off >>= 1)
        sum += __shfl_xor_sync(0xFFFFFFFFu, sum, off);
    if (L == 0) ssum[wid] = sum;
    __syncthreads();
    float tot = ssum[0];
    #pragma unroll
    for (int w = 1; w < 8; ++w) tot += ssum[w];
    const float inv = 1.f / tot;

    #pragma unroll
    for (int i = 0; i < 8; ++i) {
        const int idx = tid + i * 256;
        if (idx < Lp) orow[idx] = __float2half(vals[i] * inv);
    }
}

// ---------------------------------------------------------------------------
extern "C" void kernel_launch(void* const* d_in, const int* in_sizes, int n_in,
                              void* d_out, int out_size)
{
    const float* x  = (const float*)d_in[0];
    const float* Wq = (const float*)d_in[1];
    const float* Wk = (const float*)d_in[2];
    const float* Wv = (const float*)d_in[3];
    float* out = (float*)d_out;
    (void)in_sizes; (void)n_in; (void)out_size;

    cudaFuncSetAttribute(qkv_f16,    cudaFuncAttributeMaxDynamicSharedMemorySize, SMEM_DYN);
    cudaFuncSetAttribute(scores_f16, cudaFuncAttributeMaxDynamicSharedMemorySize, SMEM_DYN);
    cudaFuncSetAttribute(pv_f16,     cudaFuncAttributeMaxDynamicSharedMemorySize, SMEM_DYN);

    cvt_x_kernel<<<(int)(((size_t)MM * DD / 4) / 256), 256>>>(x);
    transW_kernel<<<dim3(32, 32, 3), dim3(32, 8)>>>(Wq, Wk, Wv);
    qkv_f16<<<dim3(DD / CTA_N, MM / CTA_M, 3), TPB, SMEM_DYN>>>();
    scores_f16<<<dim3(SS / CTA_N, SS / CTA_M, BB), TPB, SMEM_DYN>>>();
    softmax_kernel<<<dim3(SS, BB), 256>>>();
    pv_f16<<<dim3(DD / CTA_N, SS / CTA_M, BB), TPB, SMEM_DYN>>>(out);
}